// round 12
// baseline (speedup 1.0000x reference)
#include <cuda_runtime.h>
#include <cuda_bf16.h>
#include <math.h>
#include <stdint.h>

// Problem constants (fixed shapes)
#define NND 100000
#define NED 1600000
#define NTOT (NED + NND)           // CSR capacity: valid edges + self loops
#define NGRAPH 64
#define SCAN_B ((NND + 255) / 256) // 391 scan blocks
#define E4_B ((NED / 4 + 255) / 256)      // 1563 count/scatter blocks
#define PX_B ((NND * 16 + 255) / 256)     // 6250 prepx blocks
#define MMA_B ((NND + 127) / 128)         // 782 gemm blocks
#define GEMM_SMEM 17440

// -------- device scratch --------
__device__ __align__(16) __nv_bfloat16 g_xb[NND * 64];      // bf16 copy of x
__device__ __align__(16) __nv_bfloat16 g_hb[NND * 64];      // bf16 GEMM output (gather source)
__device__ __align__(16) __nv_bfloat16 g_ho[NND * 64];      // bf16 aggregate output
__device__ __align__(16) __nv_bfloat16 g_wt[3][2][64 * 64]; // W^T bf16 {hi, lo residual}
__device__ float g_aS[NND];
__device__ float g_aD[NND];
__device__ int   g_rowoff[NND + 1];
__device__ int   g_cursor[NND];
__device__ int   g_scanmeta[1 + SCAN_B];
__device__ __align__(8) int2 g_colev[NTOT];

__device__ __forceinline__ unsigned pack_bf16x2(float a, float b) {
    unsigned r;
    asm("cvt.rn.bf16x2.f32 %0, %1, %2;" : "=r"(r) : "f"(b), "f"(a));
    return r;
}
__device__ __forceinline__ unsigned long long ffma2(
    unsigned long long a, unsigned long long b, unsigned long long c) {
    unsigned long long d;
    asm("fma.rn.f32x2 %0, %1, %2, %3;" : "=l"(d) : "l"(a), "l"(b), "l"(c));
    return d;
}

// warp-level bf16 tensor-core MMA (valid at compute_103 — NOT tcgen05)
__device__ __forceinline__ void mma16816(float* c, uint32_t a0, uint32_t a1,
                                         uint32_t a2, uint32_t a3,
                                         uint32_t b0, uint32_t b1) {
    asm volatile(
        "mma.sync.aligned.m16n8k16.row.col.f32.bf16.bf16.f32 "
        "{%0,%1,%2,%3}, {%4,%5,%6,%7}, {%8,%9}, {%0,%1,%2,%3};"
        : "+f"(c[0]), "+f"(c[1]), "+f"(c[2]), "+f"(c[3])
        : "r"(a0), "r"(a1), "r"(a2), "r"(a3), "r"(b0), "r"(b1));
}

// ---------------------------------------------------------------------------
// GEMM body. Split-W bf16 MMA: H = A@W_hi + A@W_lo. 128 rows per block.
// ---------------------------------------------------------------------------
__device__ __forceinline__ void gemm_body(char* sm,
    const __nv_bfloat16* __restrict__ X, const __nv_bfloat16* __restrict__ Wt,
    const float* __restrict__ att, int n, int blk)
{
    float* sAtt = reinterpret_cast<float*>(sm);
    uint32_t* sWh = reinterpret_cast<uint32_t*>(sm + 544);
    uint32_t* sWl = sWh + 64 * 33;
    int tid = threadIdx.x;
    const uint32_t* Wt32 = reinterpret_cast<const uint32_t*>(Wt);
    #pragma unroll
    for (int i = tid; i < 2048; i += 256) {
        sWh[(i >> 5) * 33 + (i & 31)] = Wt32[i];
        sWl[(i >> 5) * 33 + (i & 31)] = Wt32[2048 + i];
    }
    if (tid < 129) sAtt[tid] = att[tid];
    __syncthreads();

    int warp = tid >> 5, lane = tid & 31;
    int gid = lane >> 2, tig = lane & 3;
    int r0 = blk * 128 + warp * 16 + gid;
    int r1 = r0 + 8;
    int r0c = min(r0, n - 1), r1c = min(r1, n - 1);
    const uint32_t* Xw = reinterpret_cast<const uint32_t*>(X);

    float c[8][4];
    #pragma unroll
    for (int nt = 0; nt < 8; nt++)
        #pragma unroll
        for (int q = 0; q < 4; q++) c[nt][q] = 0.0f;

    #pragma unroll
    for (int kt = 0; kt < 4; kt++) {
        uint32_t a0 = Xw[(size_t)r0c * 32 + kt * 8 + tig];
        uint32_t a1 = Xw[(size_t)r1c * 32 + kt * 8 + tig];
        uint32_t a2 = Xw[(size_t)r0c * 32 + kt * 8 + tig + 4];
        uint32_t a3 = Xw[(size_t)r1c * 32 + kt * 8 + tig + 4];
        #pragma unroll
        for (int nt = 0; nt < 8; nt++) {
            int bi = (nt * 8 + gid) * 33 + kt * 8 + tig;
            mma16816(c[nt], a0, a1, a2, a3, sWh[bi], sWh[bi + 4]);
            mma16816(c[nt], a0, a1, a2, a3, sWl[bi], sWl[bi + 4]);
        }
    }

    float ad0 = 0.0f, as0 = 0.0f, ad1 = 0.0f, as1 = 0.0f;
    #pragma unroll
    for (int nt = 0; nt < 8; nt++) {
        float w0 = sAtt[nt * 8 + tig * 2],      w1 = sAtt[nt * 8 + tig * 2 + 1];
        float v0 = sAtt[64 + nt * 8 + tig * 2], v1 = sAtt[64 + nt * 8 + tig * 2 + 1];
        ad0 += c[nt][0] * w0 + c[nt][1] * w1;
        as0 += c[nt][0] * v0 + c[nt][1] * v1;
        ad1 += c[nt][2] * w0 + c[nt][3] * w1;
        as1 += c[nt][2] * v0 + c[nt][3] * v1;
    }
    #pragma unroll
    for (int o = 1; o <= 2; o <<= 1) {
        ad0 += __shfl_xor_sync(0xffffffffu, ad0, o);
        as0 += __shfl_xor_sync(0xffffffffu, as0, o);
        ad1 += __shfl_xor_sync(0xffffffffu, ad1, o);
        as1 += __shfl_xor_sync(0xffffffffu, as1, o);
    }
    if (tig == 0 && r0 < n) { g_aD[r0] = ad0; g_aS[r0] = as0; }
    if (tig == 0 && r1 < n) { g_aD[r1] = ad1; g_aS[r1] = as1; }

    uint32_t* H32 = reinterpret_cast<uint32_t*>(g_hb);
    if (r0 < n) {
        #pragma unroll
        for (int nt = 0; nt < 8; nt++)
            H32[(size_t)r0 * 32 + nt * 4 + tig] = pack_bf16x2(c[nt][0], c[nt][1]);
    }
    if (r1 < n) {
        #pragma unroll
        for (int nt = 0; nt < 8; nt++)
            H32[(size_t)r1 * 32 + nt * 4 + tig] = pack_bf16x2(c[nt][2], c[nt][3]);
    }
}

// ---------------------------------------------------------------------------
// Scan body: decoupled lookback with warp-parallel window (32 preds/step).
// ---------------------------------------------------------------------------
__device__ __forceinline__ void scan_body(char* sm, int n, float* out,
                                          const float* __restrict__ bf)
{
    int* sh = reinterpret_cast<int*>(sm);
    volatile int* sbid  = sh + 256;
    volatile int* sprev = sh + 257;
    int tid = threadIdx.x;
    if (tid == 0) *sbid = atomicAdd(&g_scanmeta[0], 1);
    __syncthreads();
    int bid = *sbid;
    if (bid == 0 && tid < NGRAPH) out[tid] = bf[0];

    int i = bid * 256 + tid;
    int v = (i < n) ? (g_cursor[i] + 1) : 0;   // +1 = self loop
    sh[tid] = v;
    __syncthreads();
    #pragma unroll
    for (int off = 1; off < 256; off <<= 1) {
        int t = (tid >= off) ? sh[tid - off] : 0;
        __syncthreads();
        sh[tid] += t;
        __syncthreads();
    }
    int total = sh[255];

    if (bid == 0) {
        if (tid == 0) { atomicExch(&g_scanmeta[1], (total << 2) | 2); *sprev = 0; }
    } else {
        if (tid == 0) atomicExch(&g_scanmeta[1 + bid], (total << 2) | 1);
        if (tid < 32) {
            int sum = 0;
            int j = bid - 1 - tid;
            while (true) {
                int s = 0;
                if (j >= 0) {
                    do { s = atomicAdd(&g_scanmeta[1 + j], 0); } while (!(s & 3));
                }
                unsigned pm = __ballot_sync(0xffffffffu, (j >= 0) && ((s & 3) == 2));
                int lim = pm ? (__ffs(pm) - 1) : 32;
                int val = (j >= 0 && tid <= lim) ? (s >> 2) : 0;
                #pragma unroll
                for (int o = 16; o > 0; o >>= 1)
                    val += __shfl_xor_sync(0xffffffffu, val, o);
                sum += val;
                if (pm) break;
                j -= 32;
            }
            if (tid == 0) {
                atomicExch(&g_scanmeta[1 + bid], ((sum + total) << 2) | 2);
                *sprev = sum;
            }
        }
    }
    __syncthreads();
    int base = *sprev;
    if (i < n) {
        int p = base + sh[tid] - v;
        g_rowoff[i] = p;
        g_colev[p] = make_int2(i, 0);
        g_cursor[i] = p + 1;
    }
    if (bid == SCAN_B - 1 && tid == 255) g_rowoff[n] = base + total;
}

// ---------------------------------------------------------------------------
// Role bodies for edge passes / prep
// ---------------------------------------------------------------------------
__device__ __forceinline__ void count_body(const int* __restrict__ ei, int E, int blk) {
    int e4 = blk * 256 + threadIdx.x;
    if (4 * e4 < E) {
        int4 s = reinterpret_cast<const int4*>(ei)[e4];
        int4 d = reinterpret_cast<const int4*>(ei + E)[e4];
        if (s.x != d.x) atomicAdd(&g_cursor[d.x], 1);
        if (s.y != d.y) atomicAdd(&g_cursor[d.y], 1);
        if (s.z != d.z) atomicAdd(&g_cursor[d.z], 1);
        if (s.w != d.w) atomicAdd(&g_cursor[d.w], 1);
    }
}
__device__ __forceinline__ void scatter_body(const int* __restrict__ ei,
                                             const float* __restrict__ ea, int E, int blk) {
    int e4 = blk * 256 + threadIdx.x;
    if (4 * e4 < E) {
        int4 s = reinterpret_cast<const int4*>(ei)[e4];
        int4 d = reinterpret_cast<const int4*>(ei + E)[e4];
        float4 a = reinterpret_cast<const float4*>(ea)[e4];
        if (s.x != d.x) { int p = atomicAdd(&g_cursor[d.x], 1); g_colev[p] = make_int2(s.x, __float_as_int(a.x)); }
        if (s.y != d.y) { int p = atomicAdd(&g_cursor[d.y], 1); g_colev[p] = make_int2(s.y, __float_as_int(a.y)); }
        if (s.z != d.z) { int p = atomicAdd(&g_cursor[d.z], 1); g_colev[p] = make_int2(s.z, __float_as_int(a.z)); }
        if (s.w != d.w) { int p = atomicAdd(&g_cursor[d.w], 1); g_colev[p] = make_int2(s.w, __float_as_int(a.w)); }
    }
}
__device__ __forceinline__ void prepx_body(const float* __restrict__ x, int blk) {
    int i = blk * 256 + threadIdx.x;
    if (4 * i < NND * 64) {
        float4 v = reinterpret_cast<const float4*>(x)[i];
        uint2 o;
        o.x = pack_bf16x2(v.x, v.y);
        o.y = pack_bf16x2(v.z, v.w);
        reinterpret_cast<uint2*>(g_xb)[i] = o;
    }
}
__device__ __forceinline__ void prepw_body(const float* __restrict__ W, int layer) {
    __nv_bfloat16* hi = g_wt[layer][0];
    __nv_bfloat16* lo = g_wt[layer][1];
    for (int e = threadIdx.x; e < 64 * 64; e += 256) {
        int nn = e >> 6, kk = e & 63;
        float w = W[kk * 64 + nn];
        __nv_bfloat16 h = __float2bfloat16(w);
        hi[nn * 64 + kk] = h;
        lo[nn * 64 + kk] = __float2bfloat16(w - __bfloat162float(h));
    }
}

// ---------------------------------------------------------------------------
// Fused launches (block-role split = overlap without streams)
// ---------------------------------------------------------------------------
__global__ __launch_bounds__(256) void k_prep_count(
    const float* __restrict__ x, const float* __restrict__ W0,
    const float* __restrict__ W1, const float* __restrict__ W2,
    const int* __restrict__ ei, int E)
{
    int b = blockIdx.x;
    if (b < E4_B) count_body(ei, E, b);
    else if (b < E4_B + 3) prepw_body(b == E4_B ? W0 : (b == E4_B + 1 ? W1 : W2), b - E4_B);
    else prepx_body(x, b - E4_B - 3);
}

__global__ __launch_bounds__(256) void k_scan_lb(int n, float* out, const float* __restrict__ bf) {
    __shared__ __align__(16) char sm[1040];
    scan_body(sm, n, out, bf);
}

__global__ __launch_bounds__(256) void k_scatter_gemm(
    const int* __restrict__ ei, const float* __restrict__ ea, int E,
    const __nv_bfloat16* __restrict__ X, const __nv_bfloat16* __restrict__ Wt,
    const float* __restrict__ att, int n)
{
    __shared__ __align__(16) char sm[GEMM_SMEM];
    int b = blockIdx.x;
    if (b < E4_B) scatter_body(ei, ea, E, b);
    else gemm_body(sm, X, Wt, att, n, b - E4_B);
}

__global__ __launch_bounds__(256) void k_gemm_mma(
    const __nv_bfloat16* __restrict__ X, const __nv_bfloat16* __restrict__ Wt,
    const float* __restrict__ att, int n)
{
    __shared__ __align__(16) char sm[GEMM_SMEM];
    gemm_body(sm, X, Wt, att, n, blockIdx.x);
}

// ---------------------------------------------------------------------------
// Aggregation: warp per node, single pass. Round-11 profile: issue-bound,
// ALU 40% (shuffle broadcasts). Now: (offset,w) staged in per-warp smem
// (uniform LDS.64 broadcast, no SHFL), bf16x2->f32x2 via shift/mask (exact),
// one packed FFMA2 per edge instead of 2 FFMA.
// ---------------------------------------------------------------------------
template<bool FINAL>
__global__ __launch_bounds__(256) void k_aggregate(
    const float* __restrict__ att, const float* __restrict__ bias,
    unsigned* __restrict__ OUT,
    const int* __restrict__ batch, const float* __restrict__ Wf,
    float* __restrict__ out, int n)
{
    __shared__ float sh[NGRAPH];
    __shared__ float sWf[64];
    __shared__ __align__(8) int2 sce[8][32];   // per-warp staging: {H word offset, w bits}
    int tid = threadIdx.x;
    if (FINAL) {
        if (tid < NGRAPH) sh[tid] = 0.0f;
        if (tid < 64) sWf[tid] = Wf[tid];
        __syncthreads();
    }

    int warp = tid >> 5;
    int gwarp = (blockIdx.x * blockDim.x + tid) >> 5;
    int lane = tid & 31;
    bool active = gwarp < n;

    unsigned long long acc = 0ULL;   // packed {sx, sy}
    float dl = 0.0f;

    if (active) {
        int start = g_rowoff[gwarp];
        int end   = g_rowoff[gwarp + 1];
        float attE = __ldg(&att[128]);
        float adn  = g_aD[gwarp];
        const unsigned* Hw = reinterpret_cast<const unsigned*>(g_hb) + lane;

        for (int base = start; base < end; base += 32) {
            int cn = min(32, end - base);
            int off = 0;
            float w = 0.0f;
            if (lane < cn) {
                int2 ce = __ldg(&g_colev[base + lane]);
                off = ce.x * 32;
                float e = __int_as_float(ce.y);
                float l = adn + __ldg(&g_aS[ce.x]) + e * attE;
                l = (l >= 0.0f) ? l : 0.2f * l;
                w = __expf(l);
            }
            dl += w;
            __syncwarp();
            sce[warp][lane] = make_int2(off, __float_as_int(w));
            __syncwarp();

            #pragma unroll 4
            for (int j = 0; j < cn; j++) {
                int2 t = sce[warp][j];
                unsigned v = __ldg(Hw + (unsigned)t.x);
                unsigned flo = v << 16;
                unsigned fhi = v & 0xffff0000u;
                unsigned long long f2, w2;
                asm("mov.b64 %0, {%1,%2};" : "=l"(f2) : "r"(flo), "r"(fhi));
                asm("mov.b64 %0, {%1,%1};" : "=l"(w2) : "r"(t.y));
                acc = ffma2(w2, f2, acc);
            }
        }
    }

    float dsum = dl;
    #pragma unroll
    for (int o = 16; o > 0; o >>= 1)
        dsum += __shfl_xor_sync(0xffffffffu, dsum, o);

    if (active) {
        float sx, sy;
        asm("mov.b64 {%0,%1}, %2;" : "=f"(sx), "=f"(sy) : "l"(acc));
        float inv = 1.0f / dsum;
        float2 bv = __ldg(reinterpret_cast<const float2*>(bias) + lane);
        float rx = fmaxf(sx * inv + bv.x, 0.0f);
        float ry = fmaxf(sy * inv + bv.y, 0.0f);
        if (!FINAL) {
            OUT[(size_t)gwarp * 32 + lane] = pack_bf16x2(rx, ry);
        } else {
            float v = rx * sWf[2 * lane] + ry * sWf[2 * lane + 1];
            #pragma unroll
            for (int o = 16; o > 0; o >>= 1)
                v += __shfl_down_sync(0xffffffffu, v, o);
            if (lane == 0) atomicAdd(&sh[batch[gwarp]], v);
        }
    }
    if (FINAL) {
        __syncthreads();
        if (tid < NGRAPH && sh[tid] != 0.0f) atomicAdd(&out[tid], sh[tid]);
    }
}

// ---------------------------------------------------------------------------
extern "C" void kernel_launch(void* const* d_in, const int* in_sizes, int n_in,
                              void* d_out, int out_size)
{
    const float* x   = (const float*)d_in[0];
    const int*   ei  = (const int*)d_in[1];
    const float* ea  = (const float*)d_in[2];
    const int*   bat = (const int*)d_in[3];
    const float* W[3]   = {(const float*)d_in[4], (const float*)d_in[7], (const float*)d_in[10]};
    const float* att[3] = {(const float*)d_in[5], (const float*)d_in[8], (const float*)d_in[11]};
    const float* b[3]   = {(const float*)d_in[6], (const float*)d_in[9], (const float*)d_in[12]};
    const float* Wf = (const float*)d_in[13];
    const float* bf = (const float*)d_in[14];
    float* out = (float*)d_out;

    __nv_bfloat16 *xb, *ho, *wt;
    cudaGetSymbolAddress((void**)&xb, g_xb);
    cudaGetSymbolAddress((void**)&ho, g_ho);
    cudaGetSymbolAddress((void**)&wt, g_wt);
    int* cur;
    cudaGetSymbolAddress((void**)&cur, g_cursor);
    int* meta;
    cudaGetSymbolAddress((void**)&meta, g_scanmeta);

    const int N = NND, E = NED;
    int warpBlocks = (N + 7) / 8;              // 12500

    // --- prep + CSR build (fused for overlap) ---
    cudaMemsetAsync(cur, 0, N * sizeof(int), 0);
    cudaMemsetAsync(meta, 0, (1 + SCAN_B) * sizeof(int), 0);
    k_prep_count<<<E4_B + 3 + PX_B, 256>>>(x, W[0], W[1], W[2], ei, E);
    k_scan_lb<<<SCAN_B, 256>>>(N, out, bf);
    k_scatter_gemm<<<E4_B + MMA_B, 256>>>(ei, ea, E, xb, wt, att[0], N);

    // --- layer 0 aggregate ---
    k_aggregate<false><<<warpBlocks, 256>>>(att[0], b[0], (unsigned*)ho, bat, Wf, out, N);
    // --- layer 1 ---
    k_gemm_mma<<<MMA_B, 256>>>(ho, wt + 2 * 64 * 64, att[1], N);
    k_aggregate<false><<<warpBlocks, 256>>>(att[1], b[1], (unsigned*)ho, bat, Wf, out, N);
    // --- layer 2 (fused pool + head) ---
    k_gemm_mma<<<MMA_B, 256>>>(ho, wt + 4 * 64 * 64, att[2], N);
    k_aggregate<true><<<warpBlocks, 256>>>(att[2], b[2], nullptr, bat, Wf, out, N);
}

// round 13
// speedup vs baseline: 1.0017x; 1.0017x over previous
#include <cuda_runtime.h>
#include <cuda_bf16.h>
#include <math.h>
#include <stdint.h>

// Problem constants (fixed shapes)
#define NND 100000
#define NED 1600000
#define NTOT (NED + NND)           // CSR capacity: valid edges + self loops
#define NGRAPH 64
#define SCAN_B ((NND + 255) / 256) // 391 scan blocks
#define E4_B ((NED / 4 + 255) / 256)      // 1563 count/scatter blocks
#define PX_B ((NND * 16 + 255) / 256)     // 6250 prepx blocks
#define MMA_B ((NND + 127) / 128)         // 782 gemm blocks
#define GEMM_SMEM 17440

// -------- device scratch --------
__device__ __align__(16) __nv_bfloat16 g_xb[NND * 64];      // bf16 copy of x
__device__ __align__(16) __nv_bfloat16 g_hb[NND * 64];      // bf16 GEMM output (gather source)
__device__ __align__(16) __nv_bfloat16 g_ho[NND * 64];      // bf16 aggregate output
__device__ __align__(16) __nv_bfloat16 g_wt[3][2][64 * 64]; // W^T bf16 {hi, lo residual}
__device__ float g_aS[NND];
__device__ float g_aD[NND];
__device__ int   g_rowoff[NND + 1];
__device__ int   g_cursor[NND];
__device__ int   g_scanmeta[1 + SCAN_B];
__device__ __align__(8) int2 g_colev[NTOT];

__device__ __forceinline__ unsigned pack_bf16x2(float a, float b) {
    unsigned r;
    asm("cvt.rn.bf16x2.f32 %0, %1, %2;" : "=r"(r) : "f"(b), "f"(a));
    return r;
}

// warp-level bf16 tensor-core MMA (valid at compute_103 — NOT tcgen05)
__device__ __forceinline__ void mma16816(float* c, uint32_t a0, uint32_t a1,
                                         uint32_t a2, uint32_t a3,
                                         uint32_t b0, uint32_t b1) {
    asm volatile(
        "mma.sync.aligned.m16n8k16.row.col.f32.bf16.bf16.f32 "
        "{%0,%1,%2,%3}, {%4,%5,%6,%7}, {%8,%9}, {%0,%1,%2,%3};"
        : "+f"(c[0]), "+f"(c[1]), "+f"(c[2]), "+f"(c[3])
        : "r"(a0), "r"(a1), "r"(a2), "r"(a3), "r"(b0), "r"(b1));
}

// ---------------------------------------------------------------------------
// GEMM body. Split-W bf16 MMA: H = A@W_hi + A@W_lo. 128 rows per block.
// ---------------------------------------------------------------------------
__device__ __forceinline__ void gemm_body(char* sm,
    const __nv_bfloat16* __restrict__ X, const __nv_bfloat16* __restrict__ Wt,
    const float* __restrict__ att, int n, int blk)
{
    float* sAtt = reinterpret_cast<float*>(sm);
    uint32_t* sWh = reinterpret_cast<uint32_t*>(sm + 544);
    uint32_t* sWl = sWh + 64 * 33;
    int tid = threadIdx.x;
    const uint32_t* Wt32 = reinterpret_cast<const uint32_t*>(Wt);
    #pragma unroll
    for (int i = tid; i < 2048; i += 256) {
        sWh[(i >> 5) * 33 + (i & 31)] = Wt32[i];
        sWl[(i >> 5) * 33 + (i & 31)] = Wt32[2048 + i];
    }
    if (tid < 129) sAtt[tid] = att[tid];
    __syncthreads();

    int warp = tid >> 5, lane = tid & 31;
    int gid = lane >> 2, tig = lane & 3;
    int r0 = blk * 128 + warp * 16 + gid;
    int r1 = r0 + 8;
    int r0c = min(r0, n - 1), r1c = min(r1, n - 1);
    const uint32_t* Xw = reinterpret_cast<const uint32_t*>(X);

    float c[8][4];
    #pragma unroll
    for (int nt = 0; nt < 8; nt++)
        #pragma unroll
        for (int q = 0; q < 4; q++) c[nt][q] = 0.0f;

    #pragma unroll
    for (int kt = 0; kt < 4; kt++) {
        uint32_t a0 = Xw[(size_t)r0c * 32 + kt * 8 + tig];
        uint32_t a1 = Xw[(size_t)r1c * 32 + kt * 8 + tig];
        uint32_t a2 = Xw[(size_t)r0c * 32 + kt * 8 + tig + 4];
        uint32_t a3 = Xw[(size_t)r1c * 32 + kt * 8 + tig + 4];
        #pragma unroll
        for (int nt = 0; nt < 8; nt++) {
            int bi = (nt * 8 + gid) * 33 + kt * 8 + tig;
            mma16816(c[nt], a0, a1, a2, a3, sWh[bi], sWh[bi + 4]);
            mma16816(c[nt], a0, a1, a2, a3, sWl[bi], sWl[bi + 4]);
        }
    }

    float ad0 = 0.0f, as0 = 0.0f, ad1 = 0.0f, as1 = 0.0f;
    #pragma unroll
    for (int nt = 0; nt < 8; nt++) {
        float w0 = sAtt[nt * 8 + tig * 2],      w1 = sAtt[nt * 8 + tig * 2 + 1];
        float v0 = sAtt[64 + nt * 8 + tig * 2], v1 = sAtt[64 + nt * 8 + tig * 2 + 1];
        ad0 += c[nt][0] * w0 + c[nt][1] * w1;
        as0 += c[nt][0] * v0 + c[nt][1] * v1;
        ad1 += c[nt][2] * w0 + c[nt][3] * w1;
        as1 += c[nt][2] * v0 + c[nt][3] * v1;
    }
    #pragma unroll
    for (int o = 1; o <= 2; o <<= 1) {
        ad0 += __shfl_xor_sync(0xffffffffu, ad0, o);
        as0 += __shfl_xor_sync(0xffffffffu, as0, o);
        ad1 += __shfl_xor_sync(0xffffffffu, ad1, o);
        as1 += __shfl_xor_sync(0xffffffffu, as1, o);
    }
    if (tig == 0 && r0 < n) { g_aD[r0] = ad0; g_aS[r0] = as0; }
    if (tig == 0 && r1 < n) { g_aD[r1] = ad1; g_aS[r1] = as1; }

    uint32_t* H32 = reinterpret_cast<uint32_t*>(g_hb);
    if (r0 < n) {
        #pragma unroll
        for (int nt = 0; nt < 8; nt++)
            H32[(size_t)r0 * 32 + nt * 4 + tig] = pack_bf16x2(c[nt][0], c[nt][1]);
    }
    if (r1 < n) {
        #pragma unroll
        for (int nt = 0; nt < 8; nt++)
            H32[(size_t)r1 * 32 + nt * 4 + tig] = pack_bf16x2(c[nt][2], c[nt][3]);
    }
}

// ---------------------------------------------------------------------------
// Scan body: decoupled lookback with warp-parallel window (32 preds/step).
// ---------------------------------------------------------------------------
__device__ __forceinline__ void scan_body(char* sm, int n, float* out,
                                          const float* __restrict__ bf)
{
    int* sh = reinterpret_cast<int*>(sm);
    volatile int* sbid  = sh + 256;
    volatile int* sprev = sh + 257;
    int tid = threadIdx.x;
    if (tid == 0) *sbid = atomicAdd(&g_scanmeta[0], 1);
    __syncthreads();
    int bid = *sbid;
    if (bid == 0 && tid < NGRAPH) out[tid] = bf[0];

    int i = bid * 256 + tid;
    int v = (i < n) ? (g_cursor[i] + 1) : 0;   // +1 = self loop
    sh[tid] = v;
    __syncthreads();
    #pragma unroll
    for (int off = 1; off < 256; off <<= 1) {
        int t = (tid >= off) ? sh[tid - off] : 0;
        __syncthreads();
        sh[tid] += t;
        __syncthreads();
    }
    int total = sh[255];

    if (bid == 0) {
        if (tid == 0) { atomicExch(&g_scanmeta[1], (total << 2) | 2); *sprev = 0; }
    } else {
        if (tid == 0) atomicExch(&g_scanmeta[1 + bid], (total << 2) | 1);
        if (tid < 32) {
            int sum = 0;
            int j = bid - 1 - tid;
            while (true) {
                int s = 0;
                if (j >= 0) {
                    do { s = atomicAdd(&g_scanmeta[1 + j], 0); } while (!(s & 3));
                }
                unsigned pm = __ballot_sync(0xffffffffu, (j >= 0) && ((s & 3) == 2));
                int lim = pm ? (__ffs(pm) - 1) : 32;
                int val = (j >= 0 && tid <= lim) ? (s >> 2) : 0;
                #pragma unroll
                for (int o = 16; o > 0; o >>= 1)
                    val += __shfl_xor_sync(0xffffffffu, val, o);
                sum += val;
                if (pm) break;
                j -= 32;
            }
            if (tid == 0) {
                atomicExch(&g_scanmeta[1 + bid], ((sum + total) << 2) | 2);
                *sprev = sum;
            }
        }
    }
    __syncthreads();
    int base = *sprev;
    if (i < n) {
        int p = base + sh[tid] - v;
        g_rowoff[i] = p;
        g_colev[p] = make_int2(i, 0);
        g_cursor[i] = p + 1;
    }
    if (bid == SCAN_B - 1 && tid == 255) g_rowoff[n] = base + total;
}

// ---------------------------------------------------------------------------
// Role bodies for edge passes / prep
// ---------------------------------------------------------------------------
__device__ __forceinline__ void count_body(const int* __restrict__ ei, int E, int blk) {
    int e4 = blk * 256 + threadIdx.x;
    if (4 * e4 < E) {
        int4 s = reinterpret_cast<const int4*>(ei)[e4];
        int4 d = reinterpret_cast<const int4*>(ei + E)[e4];
        if (s.x != d.x) atomicAdd(&g_cursor[d.x], 1);
        if (s.y != d.y) atomicAdd(&g_cursor[d.y], 1);
        if (s.z != d.z) atomicAdd(&g_cursor[d.z], 1);
        if (s.w != d.w) atomicAdd(&g_cursor[d.w], 1);
    }
}
__device__ __forceinline__ void scatter_body(const int* __restrict__ ei,
                                             const float* __restrict__ ea, int E, int blk) {
    int e4 = blk * 256 + threadIdx.x;
    if (4 * e4 < E) {
        int4 s = reinterpret_cast<const int4*>(ei)[e4];
        int4 d = reinterpret_cast<const int4*>(ei + E)[e4];
        float4 a = reinterpret_cast<const float4*>(ea)[e4];
        if (s.x != d.x) { int p = atomicAdd(&g_cursor[d.x], 1); g_colev[p] = make_int2(s.x, __float_as_int(a.x)); }
        if (s.y != d.y) { int p = atomicAdd(&g_cursor[d.y], 1); g_colev[p] = make_int2(s.y, __float_as_int(a.y)); }
        if (s.z != d.z) { int p = atomicAdd(&g_cursor[d.z], 1); g_colev[p] = make_int2(s.z, __float_as_int(a.z)); }
        if (s.w != d.w) { int p = atomicAdd(&g_cursor[d.w], 1); g_colev[p] = make_int2(s.w, __float_as_int(a.w)); }
    }
}
__device__ __forceinline__ void prepx_body(const float* __restrict__ x, int blk) {
    int i = blk * 256 + threadIdx.x;
    if (4 * i < NND * 64) {
        float4 v = reinterpret_cast<const float4*>(x)[i];
        uint2 o;
        o.x = pack_bf16x2(v.x, v.y);
        o.y = pack_bf16x2(v.z, v.w);
        reinterpret_cast<uint2*>(g_xb)[i] = o;
    }
}
__device__ __forceinline__ void prepw_body(const float* __restrict__ W, int layer) {
    __nv_bfloat16* hi = g_wt[layer][0];
    __nv_bfloat16* lo = g_wt[layer][1];
    for (int e = threadIdx.x; e < 64 * 64; e += 256) {
        int nn = e >> 6, kk = e & 63;
        float w = W[kk * 64 + nn];
        __nv_bfloat16 h = __float2bfloat16(w);
        hi[nn * 64 + kk] = h;
        lo[nn * 64 + kk] = __float2bfloat16(w - __bfloat162float(h));
    }
}

// ---------------------------------------------------------------------------
// Fused launches (block-role split = overlap without streams)
// ---------------------------------------------------------------------------
__global__ __launch_bounds__(256) void k_prep_count(
    const float* __restrict__ x, const float* __restrict__ W0,
    const float* __restrict__ W1, const float* __restrict__ W2,
    const int* __restrict__ ei, int E)
{
    int b = blockIdx.x;
    if (b < E4_B) count_body(ei, E, b);
    else if (b < E4_B + 3) prepw_body(b == E4_B ? W0 : (b == E4_B + 1 ? W1 : W2), b - E4_B);
    else prepx_body(x, b - E4_B - 3);
}

__global__ __launch_bounds__(256) void k_scan_lb(int n, float* out, const float* __restrict__ bf) {
    __shared__ __align__(16) char sm[1040];
    scan_body(sm, n, out, bf);
}

__global__ __launch_bounds__(256) void k_scatter_gemm(
    const int* __restrict__ ei, const float* __restrict__ ea, int E,
    const __nv_bfloat16* __restrict__ X, const __nv_bfloat16* __restrict__ Wt,
    const float* __restrict__ att, int n)
{
    __shared__ __align__(16) char sm[GEMM_SMEM];
    int b = blockIdx.x;
    if (b < E4_B) scatter_body(ei, ea, E, b);
    else gemm_body(sm, X, Wt, att, n, b - E4_B);
}

__global__ __launch_bounds__(256) void k_gemm_mma(
    const __nv_bfloat16* __restrict__ X, const __nv_bfloat16* __restrict__ Wt,
    const float* __restrict__ att, int n)
{
    __shared__ __align__(16) char sm[GEMM_SMEM];
    gemm_body(sm, X, Wt, att, n, blockIdx.x);
}

// ---------------------------------------------------------------------------
// Aggregation: warp per node, single pass (logits bounded -> exp safe).
// Round-11 shuffle-broadcast structure (best known) with gather MLP deepened
// 4 -> 8: eight up-front (c,w) broadcasts + 8 independent LDGs per wave,
// halving per-node load-latency exposure (round-12 showed stall-bound).
// ---------------------------------------------------------------------------
template<bool FINAL>
__global__ __launch_bounds__(256) void k_aggregate(
    const float* __restrict__ att, const float* __restrict__ bias,
    unsigned* __restrict__ OUT,
    const int* __restrict__ batch, const float* __restrict__ Wf,
    float* __restrict__ out, int n)
{
    __shared__ float sh[NGRAPH];
    __shared__ float sWf[64];
    int tid = threadIdx.x;
    if (FINAL) {
        if (tid < NGRAPH) sh[tid] = 0.0f;
        if (tid < 64) sWf[tid] = Wf[tid];
        __syncthreads();
    }

    int gwarp = (blockIdx.x * blockDim.x + tid) >> 5;
    int lane = tid & 31;
    bool active = gwarp < n;

    float sx = 0.0f, sy = 0.0f, dl = 0.0f;

    if (active) {
        int start = g_rowoff[gwarp];
        int end   = g_rowoff[gwarp + 1];
        float attE = __ldg(&att[128]);
        float adn  = g_aD[gwarp];
        const unsigned* Hw = reinterpret_cast<const unsigned*>(g_hb);

        for (int base = start; base < end; base += 32) {
            int cn = min(32, end - base);
            int c = 0;
            float w = 0.0f;
            if (lane < cn) {
                int2 ce = __ldg(&g_colev[base + lane]);
                c = ce.x;
                float e = __int_as_float(ce.y);
                float l = adn + __ldg(&g_aS[c]) + e * attE;
                l = (l >= 0.0f) ? l : 0.2f * l;
                w = __expf(l);
            }
            dl += w;

            int j = 0;
            for (; j + 8 <= cn; j += 8) {
                int cc[8]; float ww[8]; unsigned vv[8];
                #pragma unroll
                for (int u = 0; u < 8; u++) {
                    cc[u] = __shfl_sync(0xffffffffu, c, j + u);
                    ww[u] = __shfl_sync(0xffffffffu, w, j + u);
                }
                #pragma unroll
                for (int u = 0; u < 8; u++)
                    vv[u] = __ldg(&Hw[(size_t)cc[u] * 32 + lane]);
                #pragma unroll
                for (int u = 0; u < 8; u++) {
                    float2 f = __bfloat1622float2(*reinterpret_cast<__nv_bfloat162*>(&vv[u]));
                    sx += ww[u] * f.x;
                    sy += ww[u] * f.y;
                }
            }
            for (; j + 4 <= cn; j += 4) {
                int cc[4]; float ww[4]; unsigned vv[4];
                #pragma unroll
                for (int u = 0; u < 4; u++) {
                    cc[u] = __shfl_sync(0xffffffffu, c, j + u);
                    ww[u] = __shfl_sync(0xffffffffu, w, j + u);
                }
                #pragma unroll
                for (int u = 0; u < 4; u++)
                    vv[u] = __ldg(&Hw[(size_t)cc[u] * 32 + lane]);
                #pragma unroll
                for (int u = 0; u < 4; u++) {
                    float2 f = __bfloat1622float2(*reinterpret_cast<__nv_bfloat162*>(&vv[u]));
                    sx += ww[u] * f.x;
                    sy += ww[u] * f.y;
                }
            }
            for (; j < cn; j++) {
                int cj   = __shfl_sync(0xffffffffu, c, j);
                float wj = __shfl_sync(0xffffffffu, w, j);
                unsigned v = __ldg(&Hw[(size_t)cj * 32 + lane]);
                float2 f = __bfloat1622float2(*reinterpret_cast<__nv_bfloat162*>(&v));
                sx += wj * f.x;
                sy += wj * f.y;
            }
        }
    }

    float dsum = dl;
    #pragma unroll
    for (int o = 16; o > 0; o >>= 1)
        dsum += __shfl_xor_sync(0xffffffffu, dsum, o);

    if (active) {
        float inv = 1.0f / dsum;
        float2 bv = __ldg(reinterpret_cast<const float2*>(bias) + lane);
        float rx = fmaxf(sx * inv + bv.x, 0.0f);
        float ry = fmaxf(sy * inv + bv.y, 0.0f);
        if (!FINAL) {
            OUT[(size_t)gwarp * 32 + lane] = pack_bf16x2(rx, ry);
        } else {
            float v = rx * sWf[2 * lane] + ry * sWf[2 * lane + 1];
            #pragma unroll
            for (int o = 16; o > 0; o >>= 1)
                v += __shfl_down_sync(0xffffffffu, v, o);
            if (lane == 0) atomicAdd(&sh[batch[gwarp]], v);
        }
    }
    if (FINAL) {
        __syncthreads();
        if (tid < NGRAPH && sh[tid] != 0.0f) atomicAdd(&out[tid], sh[tid]);
    }
}

// ---------------------------------------------------------------------------
extern "C" void kernel_launch(void* const* d_in, const int* in_sizes, int n_in,
                              void* d_out, int out_size)
{
    const float* x   = (const float*)d_in[0];
    const int*   ei  = (const int*)d_in[1];
    const float* ea  = (const float*)d_in[2];
    const int*   bat = (const int*)d_in[3];
    const float* W[3]   = {(const float*)d_in[4], (const float*)d_in[7], (const float*)d_in[10]};
    const float* att[3] = {(const float*)d_in[5], (const float*)d_in[8], (const float*)d_in[11]};
    const float* b[3]   = {(const float*)d_in[6], (const float*)d_in[9], (const float*)d_in[12]};
    const float* Wf = (const float*)d_in[13];
    const float* bf = (const float*)d_in[14];
    float* out = (float*)d_out;

    __nv_bfloat16 *xb, *ho, *wt;
    cudaGetSymbolAddress((void**)&xb, g_xb);
    cudaGetSymbolAddress((void**)&ho, g_ho);
    cudaGetSymbolAddress((void**)&wt, g_wt);
    int* cur;
    cudaGetSymbolAddress((void**)&cur, g_cursor);
    int* meta;
    cudaGetSymbolAddress((void**)&meta, g_scanmeta);

    const int N = NND, E = NED;
    int warpBlocks = (N + 7) / 8;              // 12500

    // --- prep + CSR build (fused for overlap) ---
    cudaMemsetAsync(cur, 0, N * sizeof(int), 0);
    cudaMemsetAsync(meta, 0, (1 + SCAN_B) * sizeof(int), 0);
    k_prep_count<<<E4_B + 3 + PX_B, 256>>>(x, W[0], W[1], W[2], ei, E);
    k_scan_lb<<<SCAN_B, 256>>>(N, out, bf);
    k_scatter_gemm<<<E4_B + MMA_B, 256>>>(ei, ea, E, xb, wt, att[0], N);

    // --- layer 0 aggregate ---
    k_aggregate<false><<<warpBlocks, 256>>>(att[0], b[0], (unsigned*)ho, bat, Wf, out, N);
    // --- layer 1 ---
    k_gemm_mma<<<MMA_B, 256>>>(ho, wt + 2 * 64 * 64, att[1], N);
    k_aggregate<false><<<warpBlocks, 256>>>(att[1], b[1], (unsigned*)ho, bat, Wf, out, N);
    // --- layer 2 (fused pool + head) ---
    k_gemm_mma<<<MMA_B, 256>>>(ho, wt + 4 * 64 * 64, att[2], N);
    k_aggregate<true><<<warpBlocks, 256>>>(att[2], b[2], nullptr, bat, Wf, out, N);
}

// round 14
// speedup vs baseline: 1.0660x; 1.0642x over previous
#include <cuda_runtime.h>
#include <cuda_bf16.h>
#include <math.h>
#include <stdint.h>

// Problem constants (fixed shapes)
#define NND 100000
#define NED 1600000
#define NTOT (NED + NND)           // CSR capacity: valid edges + self loops
#define NGRAPH 64
#define SCAN_B ((NND + 255) / 256) // 391 scan blocks
#define E4_B ((NED / 4 + 255) / 256)      // 1563 count/scatter blocks
#define PX_B ((NND * 16 + 255) / 256)     // 6250 prepx blocks
#define MMA_B ((NND + 127) / 128)         // 782 gemm blocks
#define GEMM_SMEM 17440

// -------- device scratch --------
__device__ __align__(16) __nv_bfloat16 g_xb[NND * 64];      // bf16 copy of x
__device__ __align__(16) __nv_bfloat16 g_hb[NND * 64];      // bf16 GEMM output (gather source)
__device__ __align__(16) __nv_bfloat16 g_ho[NND * 64];      // bf16 aggregate output
__device__ __align__(16) __nv_bfloat16 g_wt[3][2][64 * 64]; // W^T bf16 {hi, lo residual}
__device__ float g_aS[NND];
__device__ float g_aD[NND];
__device__ int   g_rowoff[NND + 1];
__device__ int   g_cursor[NND];
__device__ int   g_scanmeta[1 + SCAN_B];
__device__ __align__(8) int2 g_colev[NTOT];

__device__ __forceinline__ unsigned pack_bf16x2(float a, float b) {
    unsigned r;
    asm("cvt.rn.bf16x2.f32 %0, %1, %2;" : "=r"(r) : "f"(b), "f"(a));
    return r;
}
__device__ __forceinline__ unsigned long long ffma2(
    unsigned long long a, unsigned long long b, unsigned long long c) {
    unsigned long long d;
    asm("fma.rn.f32x2 %0, %1, %2, %3;" : "=l"(d) : "l"(a), "l"(b), "l"(c));
    return d;
}
__device__ __forceinline__ unsigned long long addf32x2(
    unsigned long long a, unsigned long long b) {
    unsigned long long d;
    asm("add.rn.f32x2 %0, %1, %2;" : "=l"(d) : "l"(a), "l"(b));
    return d;
}

// warp-level bf16 tensor-core MMA (valid at compute_103 — NOT tcgen05)
__device__ __forceinline__ void mma16816(float* c, uint32_t a0, uint32_t a1,
                                         uint32_t a2, uint32_t a3,
                                         uint32_t b0, uint32_t b1) {
    asm volatile(
        "mma.sync.aligned.m16n8k16.row.col.f32.bf16.bf16.f32 "
        "{%0,%1,%2,%3}, {%4,%5,%6,%7}, {%8,%9}, {%0,%1,%2,%3};"
        : "+f"(c[0]), "+f"(c[1]), "+f"(c[2]), "+f"(c[3])
        : "r"(a0), "r"(a1), "r"(a2), "r"(a3), "r"(b0), "r"(b1));
}

// ---------------------------------------------------------------------------
// GEMM body. Split-W bf16 MMA: H = A@W_hi + A@W_lo. 128 rows per block.
// ---------------------------------------------------------------------------
__device__ __forceinline__ void gemm_body(char* sm,
    const __nv_bfloat16* __restrict__ X, const __nv_bfloat16* __restrict__ Wt,
    const float* __restrict__ att, int n, int blk)
{
    float* sAtt = reinterpret_cast<float*>(sm);
    uint32_t* sWh = reinterpret_cast<uint32_t*>(sm + 544);
    uint32_t* sWl = sWh + 64 * 33;
    int tid = threadIdx.x;
    const uint32_t* Wt32 = reinterpret_cast<const uint32_t*>(Wt);
    #pragma unroll
    for (int i = tid; i < 2048; i += 256) {
        sWh[(i >> 5) * 33 + (i & 31)] = Wt32[i];
        sWl[(i >> 5) * 33 + (i & 31)] = Wt32[2048 + i];
    }
    if (tid < 129) sAtt[tid] = att[tid];
    __syncthreads();

    int warp = tid >> 5, lane = tid & 31;
    int gid = lane >> 2, tig = lane & 3;
    int r0 = blk * 128 + warp * 16 + gid;
    int r1 = r0 + 8;
    int r0c = min(r0, n - 1), r1c = min(r1, n - 1);
    const uint32_t* Xw = reinterpret_cast<const uint32_t*>(X);

    float c[8][4];
    #pragma unroll
    for (int nt = 0; nt < 8; nt++)
        #pragma unroll
        for (int q = 0; q < 4; q++) c[nt][q] = 0.0f;

    #pragma unroll
    for (int kt = 0; kt < 4; kt++) {
        uint32_t a0 = Xw[(size_t)r0c * 32 + kt * 8 + tig];
        uint32_t a1 = Xw[(size_t)r1c * 32 + kt * 8 + tig];
        uint32_t a2 = Xw[(size_t)r0c * 32 + kt * 8 + tig + 4];
        uint32_t a3 = Xw[(size_t)r1c * 32 + kt * 8 + tig + 4];
        #pragma unroll
        for (int nt = 0; nt < 8; nt++) {
            int bi = (nt * 8 + gid) * 33 + kt * 8 + tig;
            mma16816(c[nt], a0, a1, a2, a3, sWh[bi], sWh[bi + 4]);
            mma16816(c[nt], a0, a1, a2, a3, sWl[bi], sWl[bi + 4]);
        }
    }

    float ad0 = 0.0f, as0 = 0.0f, ad1 = 0.0f, as1 = 0.0f;
    #pragma unroll
    for (int nt = 0; nt < 8; nt++) {
        float w0 = sAtt[nt * 8 + tig * 2],      w1 = sAtt[nt * 8 + tig * 2 + 1];
        float v0 = sAtt[64 + nt * 8 + tig * 2], v1 = sAtt[64 + nt * 8 + tig * 2 + 1];
        ad0 += c[nt][0] * w0 + c[nt][1] * w1;
        as0 += c[nt][0] * v0 + c[nt][1] * v1;
        ad1 += c[nt][2] * w0 + c[nt][3] * w1;
        as1 += c[nt][2] * v0 + c[nt][3] * v1;
    }
    #pragma unroll
    for (int o = 1; o <= 2; o <<= 1) {
        ad0 += __shfl_xor_sync(0xffffffffu, ad0, o);
        as0 += __shfl_xor_sync(0xffffffffu, as0, o);
        ad1 += __shfl_xor_sync(0xffffffffu, ad1, o);
        as1 += __shfl_xor_sync(0xffffffffu, as1, o);
    }
    if (tig == 0 && r0 < n) { g_aD[r0] = ad0; g_aS[r0] = as0; }
    if (tig == 0 && r1 < n) { g_aD[r1] = ad1; g_aS[r1] = as1; }

    uint32_t* H32 = reinterpret_cast<uint32_t*>(g_hb);
    if (r0 < n) {
        #pragma unroll
        for (int nt = 0; nt < 8; nt++)
            H32[(size_t)r0 * 32 + nt * 4 + tig] = pack_bf16x2(c[nt][0], c[nt][1]);
    }
    if (r1 < n) {
        #pragma unroll
        for (int nt = 0; nt < 8; nt++)
            H32[(size_t)r1 * 32 + nt * 4 + tig] = pack_bf16x2(c[nt][2], c[nt][3]);
    }
}

// ---------------------------------------------------------------------------
// Scan body: decoupled lookback with warp-parallel window (32 preds/step).
// ---------------------------------------------------------------------------
__device__ __forceinline__ void scan_body(char* sm, int n, float* out,
                                          const float* __restrict__ bf)
{
    int* sh = reinterpret_cast<int*>(sm);
    volatile int* sbid  = sh + 256;
    volatile int* sprev = sh + 257;
    int tid = threadIdx.x;
    if (tid == 0) *sbid = atomicAdd(&g_scanmeta[0], 1);
    __syncthreads();
    int bid = *sbid;
    if (bid == 0 && tid < NGRAPH) out[tid] = bf[0];

    int i = bid * 256 + tid;
    int v = (i < n) ? (g_cursor[i] + 1) : 0;   // +1 = self loop
    sh[tid] = v;
    __syncthreads();
    #pragma unroll
    for (int off = 1; off < 256; off <<= 1) {
        int t = (tid >= off) ? sh[tid - off] : 0;
        __syncthreads();
        sh[tid] += t;
        __syncthreads();
    }
    int total = sh[255];

    if (bid == 0) {
        if (tid == 0) { atomicExch(&g_scanmeta[1], (total << 2) | 2); *sprev = 0; }
    } else {
        if (tid == 0) atomicExch(&g_scanmeta[1 + bid], (total << 2) | 1);
        if (tid < 32) {
            int sum = 0;
            int j = bid - 1 - tid;
            while (true) {
                int s = 0;
                if (j >= 0) {
                    do { s = atomicAdd(&g_scanmeta[1 + j], 0); } while (!(s & 3));
                }
                unsigned pm = __ballot_sync(0xffffffffu, (j >= 0) && ((s & 3) == 2));
                int lim = pm ? (__ffs(pm) - 1) : 32;
                int val = (j >= 0 && tid <= lim) ? (s >> 2) : 0;
                #pragma unroll
                for (int o = 16; o > 0; o >>= 1)
                    val += __shfl_xor_sync(0xffffffffu, val, o);
                sum += val;
                if (pm) break;
                j -= 32;
            }
            if (tid == 0) {
                atomicExch(&g_scanmeta[1 + bid], ((sum + total) << 2) | 2);
                *sprev = sum;
            }
        }
    }
    __syncthreads();
    int base = *sprev;
    if (i < n) {
        int p = base + sh[tid] - v;
        g_rowoff[i] = p;
        g_colev[p] = make_int2(i, 0);
        g_cursor[i] = p + 1;
    }
    if (bid == SCAN_B - 1 && tid == 255) g_rowoff[n] = base + total;
}

// ---------------------------------------------------------------------------
// Role bodies for edge passes / prep
// ---------------------------------------------------------------------------
__device__ __forceinline__ void count_body(const int* __restrict__ ei, int E, int blk) {
    int e4 = blk * 256 + threadIdx.x;
    if (4 * e4 < E) {
        int4 s = reinterpret_cast<const int4*>(ei)[e4];
        int4 d = reinterpret_cast<const int4*>(ei + E)[e4];
        if (s.x != d.x) atomicAdd(&g_cursor[d.x], 1);
        if (s.y != d.y) atomicAdd(&g_cursor[d.y], 1);
        if (s.z != d.z) atomicAdd(&g_cursor[d.z], 1);
        if (s.w != d.w) atomicAdd(&g_cursor[d.w], 1);
    }
}
__device__ __forceinline__ void scatter_body(const int* __restrict__ ei,
                                             const float* __restrict__ ea, int E, int blk) {
    int e4 = blk * 256 + threadIdx.x;
    if (4 * e4 < E) {
        int4 s = reinterpret_cast<const int4*>(ei)[e4];
        int4 d = reinterpret_cast<const int4*>(ei + E)[e4];
        float4 a = reinterpret_cast<const float4*>(ea)[e4];
        if (s.x != d.x) { int p = atomicAdd(&g_cursor[d.x], 1); g_colev[p] = make_int2(s.x, __float_as_int(a.x)); }
        if (s.y != d.y) { int p = atomicAdd(&g_cursor[d.y], 1); g_colev[p] = make_int2(s.y, __float_as_int(a.y)); }
        if (s.z != d.z) { int p = atomicAdd(&g_cursor[d.z], 1); g_colev[p] = make_int2(s.z, __float_as_int(a.z)); }
        if (s.w != d.w) { int p = atomicAdd(&g_cursor[d.w], 1); g_colev[p] = make_int2(s.w, __float_as_int(a.w)); }
    }
}
__device__ __forceinline__ void prepx_body(const float* __restrict__ x, int blk) {
    int i = blk * 256 + threadIdx.x;
    if (4 * i < NND * 64) {
        float4 v = reinterpret_cast<const float4*>(x)[i];
        uint2 o;
        o.x = pack_bf16x2(v.x, v.y);
        o.y = pack_bf16x2(v.z, v.w);
        reinterpret_cast<uint2*>(g_xb)[i] = o;
    }
}
__device__ __forceinline__ void prepw_body(const float* __restrict__ W, int layer) {
    __nv_bfloat16* hi = g_wt[layer][0];
    __nv_bfloat16* lo = g_wt[layer][1];
    for (int e = threadIdx.x; e < 64 * 64; e += 256) {
        int nn = e >> 6, kk = e & 63;
        float w = W[kk * 64 + nn];
        __nv_bfloat16 h = __float2bfloat16(w);
        hi[nn * 64 + kk] = h;
        lo[nn * 64 + kk] = __float2bfloat16(w - __bfloat162float(h));
    }
}

// ---------------------------------------------------------------------------
// Fused launches (block-role split = overlap without streams)
// ---------------------------------------------------------------------------
__global__ __launch_bounds__(256) void k_prep_count(
    const float* __restrict__ x, const float* __restrict__ W0,
    const float* __restrict__ W1, const float* __restrict__ W2,
    const int* __restrict__ ei, int E)
{
    int b = blockIdx.x;
    if (b < E4_B) count_body(ei, E, b);
    else if (b < E4_B + 3) prepw_body(b == E4_B ? W0 : (b == E4_B + 1 ? W1 : W2), b - E4_B);
    else prepx_body(x, b - E4_B - 3);
}

__global__ __launch_bounds__(256) void k_scan_lb(int n, float* out, const float* __restrict__ bf) {
    __shared__ __align__(16) char sm[1040];
    scan_body(sm, n, out, bf);
}

__global__ __launch_bounds__(256) void k_scatter_gemm(
    const int* __restrict__ ei, const float* __restrict__ ea, int E,
    const __nv_bfloat16* __restrict__ X, const __nv_bfloat16* __restrict__ Wt,
    const float* __restrict__ att, int n)
{
    __shared__ __align__(16) char sm[GEMM_SMEM];
    int b = blockIdx.x;
    if (b < E4_B) scatter_body(ei, ea, E, b);
    else gemm_body(sm, X, Wt, att, n, b - E4_B);
}

__global__ __launch_bounds__(256) void k_gemm_mma(
    const __nv_bfloat16* __restrict__ X, const __nv_bfloat16* __restrict__ Wt,
    const float* __restrict__ att, int n)
{
    __shared__ __align__(16) char sm[GEMM_SMEM];
    gemm_body(sm, X, Wt, att, n, blockIdx.x);
}

// ---------------------------------------------------------------------------
// Aggregation: warp per node, single pass (logits bounded -> exp safe).
// TWO edges per warp-iteration: lanes 0-15 take edge 2t, lanes 16-31 edge
// 2t+1; each lane loads a uint2 (4 features) so 16 lanes cover the 128B row.
// Halves SHFL+LDG+loop issues per edge vs round-11. Cross-half f32x2 combine
// in the epilogue. Tail edge is safe: out-of-range j sources a lane with w=0.
// ---------------------------------------------------------------------------
template<bool FINAL>
__global__ __launch_bounds__(256) void k_aggregate(
    const float* __restrict__ att, const float* __restrict__ bias,
    uint2* __restrict__ OUT,
    const int* __restrict__ batch, const float* __restrict__ Wf,
    float* __restrict__ out, int n)
{
    __shared__ float sh[NGRAPH];
    __shared__ float sWf[64];
    int tid = threadIdx.x;
    if (FINAL) {
        if (tid < NGRAPH) sh[tid] = 0.0f;
        if (tid < 64) sWf[tid] = Wf[tid];
        __syncthreads();
    }

    int gwarp = (blockIdx.x * blockDim.x + tid) >> 5;
    int lane = tid & 31;
    int sub = lane >> 4;        // which edge of the pair this half-warp takes
    int wrd = lane & 15;        // uint2 index within the 128B row
    bool active = gwarp < n;

    unsigned long long a01 = 0ULL, a23 = 0ULL;   // packed f32x2 accumulators
    float dl = 0.0f;

    if (active) {
        int start = g_rowoff[gwarp];
        int end   = g_rowoff[gwarp + 1];
        float attE = __ldg(&att[128]);
        float adn  = g_aD[gwarp];
        const uint2* Hw2 = reinterpret_cast<const uint2*>(g_hb);

        for (int base = start; base < end; base += 32) {
            int cn = min(32, end - base);
            int c = 0;
            float w = 0.0f;
            if (lane < cn) {
                int2 ce = __ldg(&g_colev[base + lane]);
                c = ce.x;
                float e = __int_as_float(ce.y);
                float l = adn + __ldg(&g_aS[c]) + e * attE;
                l = (l >= 0.0f) ? l : 0.2f * l;
                w = __expf(l);
            }
            dl += w;

            int iters = (cn + 1) >> 1;
            for (int t = 0; t < iters; t++) {
                int j = 2 * t + sub;                       // <= 31 always
                int ce_  = __shfl_sync(0xffffffffu, c, j);
                float we = __shfl_sync(0xffffffffu, w, j); // 0 for j >= cn
                uint2 v = __ldg(&Hw2[(size_t)ce_ * 16 + wrd]);
                unsigned long long w2, f01, f23;
                asm("mov.b64 %0, {%1,%1};" : "=l"(w2) : "r"(__float_as_uint(we)));
                {
                    unsigned lo = v.x << 16, hi = v.x & 0xffff0000u;
                    asm("mov.b64 %0, {%1,%2};" : "=l"(f01) : "r"(lo), "r"(hi));
                }
                {
                    unsigned lo = v.y << 16, hi = v.y & 0xffff0000u;
                    asm("mov.b64 %0, {%1,%2};" : "=l"(f23) : "r"(lo), "r"(hi));
                }
                a01 = ffma2(w2, f01, a01);
                a23 = ffma2(w2, f23, a23);
            }
        }
    }

    float dsum = dl;
    #pragma unroll
    for (int o = 16; o > 0; o >>= 1)
        dsum += __shfl_xor_sync(0xffffffffu, dsum, o);

    if (active) {
        // combine the two half-warps (both halves end with identical totals)
        a01 = addf32x2(a01, __shfl_xor_sync(0xffffffffu, a01, 16));
        a23 = addf32x2(a23, __shfl_xor_sync(0xffffffffu, a23, 16));
        float s0, s1, s2, s3;
        asm("mov.b64 {%0,%1}, %2;" : "=f"(s0), "=f"(s1) : "l"(a01));
        asm("mov.b64 {%0,%1}, %2;" : "=f"(s2), "=f"(s3) : "l"(a23));
        float inv = 1.0f / dsum;
        float4 bv = __ldg(reinterpret_cast<const float4*>(bias) + wrd);
        float r0 = fmaxf(s0 * inv + bv.x, 0.0f);
        float r1 = fmaxf(s1 * inv + bv.y, 0.0f);
        float r2 = fmaxf(s2 * inv + bv.z, 0.0f);
        float r3 = fmaxf(s3 * inv + bv.w, 0.0f);
        if (!FINAL) {
            if (sub == 0)
                OUT[(size_t)gwarp * 16 + wrd] = make_uint2(pack_bf16x2(r0, r1),
                                                           pack_bf16x2(r2, r3));
        } else {
            float v = r0 * sWf[4 * wrd] + r1 * sWf[4 * wrd + 1]
                    + r2 * sWf[4 * wrd + 2] + r3 * sWf[4 * wrd + 3];
            #pragma unroll
            for (int o = 16; o > 0; o >>= 1)
                v += __shfl_down_sync(0xffffffffu, v, o);
            if (lane == 0) atomicAdd(&sh[batch[gwarp]], v * 0.5f);  // halves duplicated
        }
    }
    if (FINAL) {
        __syncthreads();
        if (tid < NGRAPH && sh[tid] != 0.0f) atomicAdd(&out[tid], sh[tid]);
    }
}

// ---------------------------------------------------------------------------
extern "C" void kernel_launch(void* const* d_in, const int* in_sizes, int n_in,
                              void* d_out, int out_size)
{
    const float* x   = (const float*)d_in[0];
    const int*   ei  = (const int*)d_in[1];
    const float* ea  = (const float*)d_in[2];
    const int*   bat = (const int*)d_in[3];
    const float* W[3]   = {(const float*)d_in[4], (const float*)d_in[7], (const float*)d_in[10]};
    const float* att[3] = {(const float*)d_in[5], (const float*)d_in[8], (const float*)d_in[11]};
    const float* b[3]   = {(const float*)d_in[6], (const float*)d_in[9], (const float*)d_in[12]};
    const float* Wf = (const float*)d_in[13];
    const float* bf = (const float*)d_in[14];
    float* out = (float*)d_out;

    __nv_bfloat16 *xb, *ho, *wt;
    cudaGetSymbolAddress((void**)&xb, g_xb);
    cudaGetSymbolAddress((void**)&ho, g_ho);
    cudaGetSymbolAddress((void**)&wt, g_wt);
    int* cur;
    cudaGetSymbolAddress((void**)&cur, g_cursor);
    int* meta;
    cudaGetSymbolAddress((void**)&meta, g_scanmeta);

    const int N = NND, E = NED;
    int warpBlocks = (N + 7) / 8;              // 12500

    // --- prep + CSR build (fused for overlap) ---
    cudaMemsetAsync(cur, 0, N * sizeof(int), 0);
    cudaMemsetAsync(meta, 0, (1 + SCAN_B) * sizeof(int), 0);
    k_prep_count<<<E4_B + 3 + PX_B, 256>>>(x, W[0], W[1], W[2], ei, E);
    k_scan_lb<<<SCAN_B, 256>>>(N, out, bf);
    k_scatter_gemm<<<E4_B + MMA_B, 256>>>(ei, ea, E, xb, wt, att[0], N);

    // --- layer 0 aggregate ---
    k_aggregate<false><<<warpBlocks, 256>>>(att[0], b[0], (uint2*)ho, bat, Wf, out, N);
    // --- layer 1 ---
    k_gemm_mma<<<MMA_B, 256>>>(ho, wt + 2 * 64 * 64, att[1], N);
    k_aggregate<false><<<warpBlocks, 256>>>(att[1], b[1], (uint2*)ho, bat, Wf, out, N);
    // --- layer 2 (fused pool + head) ---
    k_gemm_mma<<<MMA_B, 256>>>(ho, wt + 4 * 64 * 64, att[2], N);
    k_aggregate<true><<<warpBlocks, 256>>>(att[2], b[2], nullptr, bat, Wf, out, N);
}

// round 15
// speedup vs baseline: 1.0832x; 1.0161x over previous
#include <cuda_runtime.h>
#include <cuda_bf16.h>
#include <math.h>
#include <stdint.h>

// Problem constants (fixed shapes)
#define NND 100000
#define NED 1600000
#define NTOT (NED + NND)           // CSR capacity: valid edges + self loops
#define NGRAPH 64
#define SCAN_B ((NND + 255) / 256) // 391 scan blocks
#define E4_B ((NED / 4 + 255) / 256)      // 1563 count/scatter blocks
#define PX_B ((NND * 16 + 255) / 256)     // 6250 prepx blocks
#define MMA_B ((NND + 127) / 128)         // 782 gemm blocks
#define GEMM_SMEM 17440
#define AGG_B 3125                        // aggregate blocks: 25000 warps, 4 nodes/warp

// -------- device scratch --------
__device__ __align__(16) __nv_bfloat16 g_xb[NND * 64];      // bf16 copy of x
__device__ __align__(16) __nv_bfloat16 g_hb[NND * 64];      // bf16 GEMM output (gather source)
__device__ __align__(16) __nv_bfloat16 g_ho[NND * 64];      // bf16 aggregate output
__device__ __align__(16) __nv_bfloat16 g_wt[3][2][64 * 64]; // W^T bf16 {hi, lo residual}
__device__ float g_aS[NND];
__device__ float g_aD[NND];
__device__ int   g_rowoff[NND + 1];
__device__ int   g_cursor[NND];
__device__ int   g_scanmeta[1 + SCAN_B];
__device__ __align__(8) int2 g_colev[NTOT];

__device__ __forceinline__ unsigned pack_bf16x2(float a, float b) {
    unsigned r;
    asm("cvt.rn.bf16x2.f32 %0, %1, %2;" : "=r"(r) : "f"(b), "f"(a));
    return r;
}
__device__ __forceinline__ unsigned long long ffma2(
    unsigned long long a, unsigned long long b, unsigned long long c) {
    unsigned long long d;
    asm("fma.rn.f32x2 %0, %1, %2, %3;" : "=l"(d) : "l"(a), "l"(b), "l"(c));
    return d;
}
__device__ __forceinline__ unsigned long long addf32x2(
    unsigned long long a, unsigned long long b) {
    unsigned long long d;
    asm("add.rn.f32x2 %0, %1, %2;" : "=l"(d) : "l"(a), "l"(b));
    return d;
}

// warp-level bf16 tensor-core MMA (valid at compute_103 — NOT tcgen05)
__device__ __forceinline__ void mma16816(float* c, uint32_t a0, uint32_t a1,
                                         uint32_t a2, uint32_t a3,
                                         uint32_t b0, uint32_t b1) {
    asm volatile(
        "mma.sync.aligned.m16n8k16.row.col.f32.bf16.bf16.f32 "
        "{%0,%1,%2,%3}, {%4,%5,%6,%7}, {%8,%9}, {%0,%1,%2,%3};"
        : "+f"(c[0]), "+f"(c[1]), "+f"(c[2]), "+f"(c[3])
        : "r"(a0), "r"(a1), "r"(a2), "r"(a3), "r"(b0), "r"(b1));
}

// ---------------------------------------------------------------------------
// GEMM body. Split-W bf16 MMA: H = A@W_hi + A@W_lo. 128 rows per block.
// ---------------------------------------------------------------------------
__device__ __forceinline__ void gemm_body(char* sm,
    const __nv_bfloat16* __restrict__ X, const __nv_bfloat16* __restrict__ Wt,
    const float* __restrict__ att, int n, int blk)
{
    float* sAtt = reinterpret_cast<float*>(sm);
    uint32_t* sWh = reinterpret_cast<uint32_t*>(sm + 544);
    uint32_t* sWl = sWh + 64 * 33;
    int tid = threadIdx.x;
    const uint32_t* Wt32 = reinterpret_cast<const uint32_t*>(Wt);
    #pragma unroll
    for (int i = tid; i < 2048; i += 256) {
        sWh[(i >> 5) * 33 + (i & 31)] = Wt32[i];
        sWl[(i >> 5) * 33 + (i & 31)] = Wt32[2048 + i];
    }
    if (tid < 129) sAtt[tid] = att[tid];
    __syncthreads();

    int warp = tid >> 5, lane = tid & 31;
    int gid = lane >> 2, tig = lane & 3;
    int r0 = blk * 128 + warp * 16 + gid;
    int r1 = r0 + 8;
    int r0c = min(r0, n - 1), r1c = min(r1, n - 1);
    const uint32_t* Xw = reinterpret_cast<const uint32_t*>(X);

    float c[8][4];
    #pragma unroll
    for (int nt = 0; nt < 8; nt++)
        #pragma unroll
        for (int q = 0; q < 4; q++) c[nt][q] = 0.0f;

    #pragma unroll
    for (int kt = 0; kt < 4; kt++) {
        uint32_t a0 = Xw[(size_t)r0c * 32 + kt * 8 + tig];
        uint32_t a1 = Xw[(size_t)r1c * 32 + kt * 8 + tig];
        uint32_t a2 = Xw[(size_t)r0c * 32 + kt * 8 + tig + 4];
        uint32_t a3 = Xw[(size_t)r1c * 32 + kt * 8 + tig + 4];
        #pragma unroll
        for (int nt = 0; nt < 8; nt++) {
            int bi = (nt * 8 + gid) * 33 + kt * 8 + tig;
            mma16816(c[nt], a0, a1, a2, a3, sWh[bi], sWh[bi + 4]);
            mma16816(c[nt], a0, a1, a2, a3, sWl[bi], sWl[bi + 4]);
        }
    }

    float ad0 = 0.0f, as0 = 0.0f, ad1 = 0.0f, as1 = 0.0f;
    #pragma unroll
    for (int nt = 0; nt < 8; nt++) {
        float w0 = sAtt[nt * 8 + tig * 2],      w1 = sAtt[nt * 8 + tig * 2 + 1];
        float v0 = sAtt[64 + nt * 8 + tig * 2], v1 = sAtt[64 + nt * 8 + tig * 2 + 1];
        ad0 += c[nt][0] * w0 + c[nt][1] * w1;
        as0 += c[nt][0] * v0 + c[nt][1] * v1;
        ad1 += c[nt][2] * w0 + c[nt][3] * w1;
        as1 += c[nt][2] * v0 + c[nt][3] * v1;
    }
    #pragma unroll
    for (int o = 1; o <= 2; o <<= 1) {
        ad0 += __shfl_xor_sync(0xffffffffu, ad0, o);
        as0 += __shfl_xor_sync(0xffffffffu, as0, o);
        ad1 += __shfl_xor_sync(0xffffffffu, ad1, o);
        as1 += __shfl_xor_sync(0xffffffffu, as1, o);
    }
    if (tig == 0 && r0 < n) { g_aD[r0] = ad0; g_aS[r0] = as0; }
    if (tig == 0 && r1 < n) { g_aD[r1] = ad1; g_aS[r1] = as1; }

    uint32_t* H32 = reinterpret_cast<uint32_t*>(g_hb);
    if (r0 < n) {
        #pragma unroll
        for (int nt = 0; nt < 8; nt++)
            H32[(size_t)r0 * 32 + nt * 4 + tig] = pack_bf16x2(c[nt][0], c[nt][1]);
    }
    if (r1 < n) {
        #pragma unroll
        for (int nt = 0; nt < 8; nt++)
            H32[(size_t)r1 * 32 + nt * 4 + tig] = pack_bf16x2(c[nt][2], c[nt][3]);
    }
}

// ---------------------------------------------------------------------------
// Scan body: decoupled lookback with warp-parallel window (32 preds/step).
// ---------------------------------------------------------------------------
__device__ __forceinline__ void scan_body(char* sm, int n, float* out,
                                          const float* __restrict__ bf)
{
    int* sh = reinterpret_cast<int*>(sm);
    volatile int* sbid  = sh + 256;
    volatile int* sprev = sh + 257;
    int tid = threadIdx.x;
    if (tid == 0) *sbid = atomicAdd(&g_scanmeta[0], 1);
    __syncthreads();
    int bid = *sbid;
    if (bid == 0 && tid < NGRAPH) out[tid] = bf[0];

    int i = bid * 256 + tid;
    int v = (i < n) ? (g_cursor[i] + 1) : 0;   // +1 = self loop
    sh[tid] = v;
    __syncthreads();
    #pragma unroll
    for (int off = 1; off < 256; off <<= 1) {
        int t = (tid >= off) ? sh[tid - off] : 0;
        __syncthreads();
        sh[tid] += t;
        __syncthreads();
    }
    int total = sh[255];

    if (bid == 0) {
        if (tid == 0) { atomicExch(&g_scanmeta[1], (total << 2) | 2); *sprev = 0; }
    } else {
        if (tid == 0) atomicExch(&g_scanmeta[1 + bid], (total << 2) | 1);
        if (tid < 32) {
            int sum = 0;
            int j = bid - 1 - tid;
            while (true) {
                int s = 0;
                if (j >= 0) {
                    do { s = atomicAdd(&g_scanmeta[1 + j], 0); } while (!(s & 3));
                }
                unsigned pm = __ballot_sync(0xffffffffu, (j >= 0) && ((s & 3) == 2));
                int lim = pm ? (__ffs(pm) - 1) : 32;
                int val = (j >= 0 && tid <= lim) ? (s >> 2) : 0;
                #pragma unroll
                for (int o = 16; o > 0; o >>= 1)
                    val += __shfl_xor_sync(0xffffffffu, val, o);
                sum += val;
                if (pm) break;
                j -= 32;
            }
            if (tid == 0) {
                atomicExch(&g_scanmeta[1 + bid], ((sum + total) << 2) | 2);
                *sprev = sum;
            }
        }
    }
    __syncthreads();
    int base = *sprev;
    if (i < n) {
        int p = base + sh[tid] - v;
        g_rowoff[i] = p;
        g_colev[p] = make_int2(i, 0);
        g_cursor[i] = p + 1;
    }
    if (bid == SCAN_B - 1 && tid == 255) g_rowoff[n] = base + total;
}

// ---------------------------------------------------------------------------
// Role bodies for edge passes / prep
// ---------------------------------------------------------------------------
__device__ __forceinline__ void count_body(const int* __restrict__ ei, int E, int blk) {
    int e4 = blk * 256 + threadIdx.x;
    if (4 * e4 < E) {
        int4 s = reinterpret_cast<const int4*>(ei)[e4];
        int4 d = reinterpret_cast<const int4*>(ei + E)[e4];
        if (s.x != d.x) atomicAdd(&g_cursor[d.x], 1);
        if (s.y != d.y) atomicAdd(&g_cursor[d.y], 1);
        if (s.z != d.z) atomicAdd(&g_cursor[d.z], 1);
        if (s.w != d.w) atomicAdd(&g_cursor[d.w], 1);
    }
}
__device__ __forceinline__ void scatter_body(const int* __restrict__ ei,
                                             const float* __restrict__ ea, int E, int blk) {
    int e4 = blk * 256 + threadIdx.x;
    if (4 * e4 < E) {
        int4 s = reinterpret_cast<const int4*>(ei)[e4];
        int4 d = reinterpret_cast<const int4*>(ei + E)[e4];
        float4 a = reinterpret_cast<const float4*>(ea)[e4];
        if (s.x != d.x) { int p = atomicAdd(&g_cursor[d.x], 1); g_colev[p] = make_int2(s.x, __float_as_int(a.x)); }
        if (s.y != d.y) { int p = atomicAdd(&g_cursor[d.y], 1); g_colev[p] = make_int2(s.y, __float_as_int(a.y)); }
        if (s.z != d.z) { int p = atomicAdd(&g_cursor[d.z], 1); g_colev[p] = make_int2(s.z, __float_as_int(a.z)); }
        if (s.w != d.w) { int p = atomicAdd(&g_cursor[d.w], 1); g_colev[p] = make_int2(s.w, __float_as_int(a.w)); }
    }
}
__device__ __forceinline__ void prepx_body(const float* __restrict__ x, int blk) {
    int i = blk * 256 + threadIdx.x;
    if (4 * i < NND * 64) {
        float4 v = reinterpret_cast<const float4*>(x)[i];
        uint2 o;
        o.x = pack_bf16x2(v.x, v.y);
        o.y = pack_bf16x2(v.z, v.w);
        reinterpret_cast<uint2*>(g_xb)[i] = o;
    }
}
__device__ __forceinline__ void prepw_body(const float* __restrict__ W, int layer) {
    __nv_bfloat16* hi = g_wt[layer][0];
    __nv_bfloat16* lo = g_wt[layer][1];
    for (int e = threadIdx.x; e < 64 * 64; e += 256) {
        int nn = e >> 6, kk = e & 63;
        float w = W[kk * 64 + nn];
        __nv_bfloat16 h = __float2bfloat16(w);
        hi[nn * 64 + kk] = h;
        lo[nn * 64 + kk] = __float2bfloat16(w - __bfloat162float(h));
    }
}

// ---------------------------------------------------------------------------
// Fused launches (block-role split = overlap without streams)
// ---------------------------------------------------------------------------
__global__ __launch_bounds__(256) void k_prep_count(
    const float* __restrict__ x, const float* __restrict__ W0,
    const float* __restrict__ W1, const float* __restrict__ W2,
    const int* __restrict__ ei, int E)
{
    int b = blockIdx.x;
    if (b < E4_B) count_body(ei, E, b);
    else if (b < E4_B + 3) prepw_body(b == E4_B ? W0 : (b == E4_B + 1 ? W1 : W2), b - E4_B);
    else prepx_body(x, b - E4_B - 3);
}

__global__ __launch_bounds__(256) void k_scan_lb(int n, float* out, const float* __restrict__ bf) {
    __shared__ __align__(16) char sm[1040];
    scan_body(sm, n, out, bf);
}

__global__ __launch_bounds__(256) void k_scatter_gemm(
    const int* __restrict__ ei, const float* __restrict__ ea, int E,
    const __nv_bfloat16* __restrict__ X, const __nv_bfloat16* __restrict__ Wt,
    const float* __restrict__ att, int n)
{
    __shared__ __align__(16) char sm[GEMM_SMEM];
    int b = blockIdx.x;
    if (b < E4_B) scatter_body(ei, ea, E, b);
    else gemm_body(sm, X, Wt, att, n, b - E4_B);
}

__global__ __launch_bounds__(256) void k_gemm_mma(
    const __nv_bfloat16* __restrict__ X, const __nv_bfloat16* __restrict__ Wt,
    const float* __restrict__ att, int n)
{
    __shared__ __align__(16) char sm[GEMM_SMEM];
    gemm_body(sm, X, Wt, att, n, blockIdx.x);
}

// ---------------------------------------------------------------------------
// Aggregation: 2-edges-per-iteration half-warp scheme (round 14), now with
// (a) 4 nodes per warp (warp-stride loop) to smooth Poisson-degree imbalance
//     (block finish was max over 8 single-node warps: ~1.6x inflation), and
// (b) gather loop unrolled x2 -> 2 independent LDG.64 in flight.
// ---------------------------------------------------------------------------
template<bool FINAL>
__global__ __launch_bounds__(256) void k_aggregate(
    const float* __restrict__ att, const float* __restrict__ bias,
    uint2* __restrict__ OUT,
    const int* __restrict__ batch, const float* __restrict__ Wf,
    float* __restrict__ out, int n)
{
    __shared__ float sh[NGRAPH];
    __shared__ float sWf[64];
    int tid = threadIdx.x;
    if (FINAL) {
        if (tid < NGRAPH) sh[tid] = 0.0f;
        if (tid < 64) sWf[tid] = Wf[tid];
        __syncthreads();
    }

    int warp0 = (blockIdx.x * blockDim.x + tid) >> 5;
    int nwarps = (gridDim.x * blockDim.x) >> 5;
    int lane = tid & 31;
    int sub = lane >> 4;
    int wrd = lane & 15;

    float attE = __ldg(&att[128]);
    const uint2* Hw2 = reinterpret_cast<const uint2*>(g_hb);
    float4 bv = __ldg(reinterpret_cast<const float4*>(bias) + wrd);

    for (int node = warp0; node < n; node += nwarps) {
        unsigned long long a01 = 0ULL, a23 = 0ULL;
        float dl = 0.0f;
        int start = g_rowoff[node];
        int end   = g_rowoff[node + 1];
        float adn = g_aD[node];

        for (int base = start; base < end; base += 32) {
            int cn = min(32, end - base);
            int c = 0;
            float w = 0.0f;
            if (lane < cn) {
                int2 ce = __ldg(&g_colev[base + lane]);
                c = ce.x;
                float e = __int_as_float(ce.y);
                float l = adn + __ldg(&g_aS[c]) + e * attE;
                l = (l >= 0.0f) ? l : 0.2f * l;
                w = __expf(l);
            }
            dl += w;

            int iters = (cn + 1) >> 1;
            int t = 0;
            for (; t + 2 <= iters; t += 2) {
                int j0 = 2 * t + sub;
                int j1 = 2 * t + 2 + sub;
                int cA   = __shfl_sync(0xffffffffu, c, j0);
                float wA = __shfl_sync(0xffffffffu, w, j0);
                int cB   = __shfl_sync(0xffffffffu, c, j1);
                float wB = __shfl_sync(0xffffffffu, w, j1);
                uint2 vA = __ldg(&Hw2[(size_t)cA * 16 + wrd]);
                uint2 vB = __ldg(&Hw2[(size_t)cB * 16 + wrd]);
                unsigned long long w2, f01, f23;
                asm("mov.b64 %0, {%1,%1};" : "=l"(w2) : "r"(__float_as_uint(wA)));
                { unsigned lo = vA.x << 16, hi = vA.x & 0xffff0000u;
                  asm("mov.b64 %0, {%1,%2};" : "=l"(f01) : "r"(lo), "r"(hi)); }
                { unsigned lo = vA.y << 16, hi = vA.y & 0xffff0000u;
                  asm("mov.b64 %0, {%1,%2};" : "=l"(f23) : "r"(lo), "r"(hi)); }
                a01 = ffma2(w2, f01, a01);
                a23 = ffma2(w2, f23, a23);
                asm("mov.b64 %0, {%1,%1};" : "=l"(w2) : "r"(__float_as_uint(wB)));
                { unsigned lo = vB.x << 16, hi = vB.x & 0xffff0000u;
                  asm("mov.b64 %0, {%1,%2};" : "=l"(f01) : "r"(lo), "r"(hi)); }
                { unsigned lo = vB.y << 16, hi = vB.y & 0xffff0000u;
                  asm("mov.b64 %0, {%1,%2};" : "=l"(f23) : "r"(lo), "r"(hi)); }
                a01 = ffma2(w2, f01, a01);
                a23 = ffma2(w2, f23, a23);
            }
            for (; t < iters; t++) {
                int j = 2 * t + sub;
                int ce_  = __shfl_sync(0xffffffffu, c, j);
                float we = __shfl_sync(0xffffffffu, w, j);
                uint2 v = __ldg(&Hw2[(size_t)ce_ * 16 + wrd]);
                unsigned long long w2, f01, f23;
                asm("mov.b64 %0, {%1,%1};" : "=l"(w2) : "r"(__float_as_uint(we)));
                { unsigned lo = v.x << 16, hi = v.x & 0xffff0000u;
                  asm("mov.b64 %0, {%1,%2};" : "=l"(f01) : "r"(lo), "r"(hi)); }
                { unsigned lo = v.y << 16, hi = v.y & 0xffff0000u;
                  asm("mov.b64 %0, {%1,%2};" : "=l"(f23) : "r"(lo), "r"(hi)); }
                a01 = ffma2(w2, f01, a01);
                a23 = ffma2(w2, f23, a23);
            }
        }

        float dsum = dl;
        #pragma unroll
        for (int o = 16; o > 0; o >>= 1)
            dsum += __shfl_xor_sync(0xffffffffu, dsum, o);

        a01 = addf32x2(a01, __shfl_xor_sync(0xffffffffu, a01, 16));
        a23 = addf32x2(a23, __shfl_xor_sync(0xffffffffu, a23, 16));
        float s0, s1, s2, s3;
        asm("mov.b64 {%0,%1}, %2;" : "=f"(s0), "=f"(s1) : "l"(a01));
        asm("mov.b64 {%0,%1}, %2;" : "=f"(s2), "=f"(s3) : "l"(a23));
        float inv = 1.0f / dsum;
        float r0 = fmaxf(s0 * inv + bv.x, 0.0f);
        float r1 = fmaxf(s1 * inv + bv.y, 0.0f);
        float r2 = fmaxf(s2 * inv + bv.z, 0.0f);
        float r3 = fmaxf(s3 * inv + bv.w, 0.0f);
        if (!FINAL) {
            if (sub == 0)
                OUT[(size_t)node * 16 + wrd] = make_uint2(pack_bf16x2(r0, r1),
                                                          pack_bf16x2(r2, r3));
        } else {
            float v = r0 * sWf[4 * wrd] + r1 * sWf[4 * wrd + 1]
                    + r2 * sWf[4 * wrd + 2] + r3 * sWf[4 * wrd + 3];
            #pragma unroll
            for (int o = 16; o > 0; o >>= 1)
                v += __shfl_down_sync(0xffffffffu, v, o);
            if (lane == 0) atomicAdd(&sh[batch[node]], v * 0.5f);  // halves duplicated
        }
    }
    if (FINAL) {
        __syncthreads();
        if (tid < NGRAPH && sh[tid] != 0.0f) atomicAdd(&out[tid], sh[tid]);
    }
}

// ---------------------------------------------------------------------------
extern "C" void kernel_launch(void* const* d_in, const int* in_sizes, int n_in,
                              void* d_out, int out_size)
{
    const float* x   = (const float*)d_in[0];
    const int*   ei  = (const int*)d_in[1];
    const float* ea  = (const float*)d_in[2];
    const int*   bat = (const int*)d_in[3];
    const float* W[3]   = {(const float*)d_in[4], (const float*)d_in[7], (const float*)d_in[10]};
    const float* att[3] = {(const float*)d_in[5], (const float*)d_in[8], (const float*)d_in[11]};
    const float* b[3]   = {(const float*)d_in[6], (const float*)d_in[9], (const float*)d_in[12]};
    const float* Wf = (const float*)d_in[13];
    const float* bf = (const float*)d_in[14];
    float* out = (float*)d_out;

    __nv_bfloat16 *xb, *ho, *wt;
    cudaGetSymbolAddress((void**)&xb, g_xb);
    cudaGetSymbolAddress((void**)&ho, g_ho);
    cudaGetSymbolAddress((void**)&wt, g_wt);
    int* cur;
    cudaGetSymbolAddress((void**)&cur, g_cursor);
    int* meta;
    cudaGetSymbolAddress((void**)&meta, g_scanmeta);

    const int N = NND, E = NED;

    // --- prep + CSR build (fused for overlap) ---
    cudaMemsetAsync(cur, 0, N * sizeof(int), 0);
    cudaMemsetAsync(meta, 0, (1 + SCAN_B) * sizeof(int), 0);
    k_prep_count<<<E4_B + 3 + PX_B, 256>>>(x, W[0], W[1], W[2], ei, E);
    k_scan_lb<<<SCAN_B, 256>>>(N, out, bf);
    k_scatter_gemm<<<E4_B + MMA_B, 256>>>(ei, ea, E, xb, wt, att[0], N);

    // --- layer 0 aggregate ---
    k_aggregate<false><<<AGG_B, 256>>>(att[0], b[0], (uint2*)ho, bat, Wf, out, N);
    // --- layer 1 ---
    k_gemm_mma<<<MMA_B, 256>>>(ho, wt + 2 * 64 * 64, att[1], N);
    k_aggregate<false><<<AGG_B, 256>>>(att[1], b[1], (uint2*)ho, bat, Wf, out, N);
    // --- layer 2 (fused pool + head) ---
    k_gemm_mma<<<MMA_B, 256>>>(ho, wt + 4 * 64 * 64, att[2], N);
    k_aggregate<true><<<AGG_B, 256>>>(att[2], b[2], nullptr, bat, Wf, out, N);
}